// round 13
// baseline (speedup 1.0000x reference)
#include <cuda_runtime.h>
#include <math.h>
#include <stdint.h>

#define BB 2
#define SS_ 2048
#define DD 2048
#define HH 16
#define HD 128
#define M_TOT (BB * SS_)     // 4096
#define N_QKV (3 * DD)       // 6144

__device__ float g_qkv[M_TOT * N_QKV];     // raw qkv rows
__device__ float g_att[M_TOT * DD];        // attention out rows (tf32-rounded)
__device__ float g_xfm [M_TOT * DD];       // x, fragment-major A
__device__ float g_attfm[M_TOT * DD];      // att, fragment-major A
__device__ float g_w1fm[DD * N_QKV];       // W_qkv, fragment-major B
__device__ float g_w2fm[DD * DD];          // W_out, fragment-major B

__device__ __forceinline__ uint32_t f2tf(float f) {
    uint32_t u;
    asm("cvt.rna.tf32.f32 %0, %1;" : "=r"(u) : "f"(f));
    return u;
}

// FMA-pipe exp (no MUFU): exp(x) = 2^(x*log2e), magic-number split,
// degree-5 poly on f in [-0.5,0.5] (rel err ~2.4e-6). Handles x=-inf via clamp.
__device__ __forceinline__ float fexp(float x) {
    x = fmaxf(x, -87.0f);
    const float L2E = 1.4426950408889634f;
    float y  = fmaf(x, L2E, 12582912.0f);      // round-to-nearest int in mantissa
    int   ni = __float_as_int(y);
    float nf = y - 12582912.0f;
    float f  = fmaf(x, L2E, -nf);              // f in [-0.5, 0.5]
    float p  = 0.00133335581f;
    p = fmaf(p, f, 0.00961812911f);
    p = fmaf(p, f, 0.0555041087f);
    p = fmaf(p, f, 0.240226507f);
    p = fmaf(p, f, 0.693147180f);
    p = fmaf(p, f, 1.0f);
    float scale = __int_as_float((ni - 0x4B400000 + 127) << 23);
    return scale * p;
}

__device__ __forceinline__ void mma_tf32(float* d, const uint32_t* a, const uint32_t* b) {
    asm volatile(
        "mma.sync.aligned.m16n8k8.row.col.f32.tf32.tf32.f32 "
        "{%0,%1,%2,%3}, {%4,%5,%6,%7}, {%8,%9}, {%0,%1,%2,%3};\n"
        : "+f"(d[0]), "+f"(d[1]), "+f"(d[2]), "+f"(d[3])
        : "r"(a[0]), "r"(a[1]), "r"(a[2]), "r"(a[3]), "r"(b[0]), "r"(b[1]));
}

__device__ __forceinline__ void cp16(uint32_t saddr, const float* gptr) {
    asm volatile("cp.async.cg.shared.global [%0], [%1], 16;" :: "r"(saddr), "l"(gptr));
}

// ===========================================================================
// Prep A: row-major [M,K] fp32 -> fragment-major tf32 blocks (as R12).
// ===========================================================================
__global__ __launch_bounds__(256) void prep_a_kernel(
    const float* __restrict__ src, float* __restrict__ dst, int K)
{
    __shared__ float tile[128 * 36];
    const int tid = threadIdx.x;
    const int nkc = K >> 5;
    const int mb = blockIdx.x / nkc;
    const int kc = blockIdx.x % nkc;
    const float* s0 = src + (size_t)mb * 128 * K + kc * 32;

#pragma unroll
    for (int p = 0; p < 4; p++) {
        int id = tid + p * 256;
        int row = id >> 3, c4 = (id & 7) << 2;
        float4 v = *reinterpret_cast<const float4*>(s0 + (size_t)row * K + c4);
        float* t = &tile[row * 36 + c4];
        t[0] = v.x; t[1] = v.y; t[2] = v.z; t[3] = v.w;
    }
    __syncthreads();

    float* d0 = dst + (size_t)blockIdx.x * 4096;
#pragma unroll
    for (int p = 0; p < 4; p++) {
        int q = tid + p * 256;
        int f = q >> 5;
        int l = q & 31;
        int g = l >> 2, c = l & 3;
        int mf = f >> 2, ks = f & 3;
        const float* tl = &tile[(mf * 16 + g) * 36 + ks * 8 + c];
        uint4 o;
        o.x = f2tf(tl[0]);
        o.y = f2tf(tl[8 * 36]);
        o.z = f2tf(tl[4]);
        o.w = f2tf(tl[8 * 36 + 4]);
        *reinterpret_cast<uint4*>(d0 + q * 4) = o;
    }
}

// ===========================================================================
// Prep B: row-major W[K,N] fp32 -> fragment-major tf32 blocks (as R12).
// ===========================================================================
__global__ __launch_bounds__(256) void prep_b_kernel(
    const float* __restrict__ src, float* __restrict__ dst, int N, int K)
{
    __shared__ float tile[32 * 132];
    const int tid = threadIdx.x;
    const int nkc = K >> 5;
    const int nb = blockIdx.x / nkc;
    const int kc = blockIdx.x % nkc;
    const float* s0 = src + (size_t)(kc * 32) * N + nb * 128;

#pragma unroll
    for (int p = 0; p < 4; p++) {
        int id = tid + p * 256;
        int k = id >> 5, n4 = (id & 31) << 2;
        float4 v = *reinterpret_cast<const float4*>(s0 + (size_t)k * N + n4);
        *reinterpret_cast<float4*>(&tile[k * 132 + n4]) = v;
    }
    __syncthreads();

    float* d0 = dst + (size_t)blockIdx.x * 4096;
#pragma unroll
    for (int p = 0; p < 4; p++) {
        int q = tid + p * 256;
        int fb = q >> 4;
        int ks = fb >> 4, n8 = fb & 15;
        int o4 = (q & 15) << 2;
        uint4 o;
        uint32_t* ov = reinterpret_cast<uint32_t*>(&o);
#pragma unroll
        for (int i = 0; i < 4; i++) {
            int off = o4 + i;
            int g = off >> 3, c = (off & 7) >> 1, u = off & 1;
            ov[i] = f2tf(tile[(ks * 8 + u * 4 + c) * 132 + n8 * 8 + g]);
        }
        *reinterpret_cast<uint4*>(d0 + q * 4) = o;
    }
}

// ===========================================================================
// TF32 mma.sync GEMM, fragment-major cp.async staging + register
// double-buffered fragments (prefetch ks+1 LDS under ks mma issue).
// ===========================================================================
#define AFRAG_FLOATS 4224                 // 32 frags * 132  (528 B, 16-aligned)
#define BFRAG_FLOATS 4352                 // 64 frags * 68   (272 B, 16-aligned)
#define STAGE_FLOATS (AFRAG_FLOATS + BFRAG_FLOATS)
#define GEMM_SMEM_BYTES (2 * STAGE_FLOATS * 4)   // 68608

__global__ __launch_bounds__(256) void gemm_fm_kernel(
    const float* __restrict__ Afm, const float* __restrict__ Bfm,
    const float* __restrict__ bias, float* __restrict__ C,
    int M, int N, int K)
{
    extern __shared__ float sh[];
    uint32_t smb;
    asm("{ .reg .u64 t; cvta.to.shared.u64 t, %1; cvt.u32.u64 %0, t; }"
        : "=r"(smb) : "l"(sh));

    const int tid  = threadIdx.x;
    const int lane = tid & 31;
    const int wid  = tid >> 5;
    const int wm   = wid & 1;
    const int wn   = wid >> 1;
    const int g    = lane >> 2;
    const int c    = lane & 3;

    const int nkc = K >> 5;
    const int mb  = blockIdx.y;
    const int nb  = blockIdx.x;
    const float* Ab = Afm + (size_t)mb * nkc * 4096;
    const float* Bb = Bfm + (size_t)nb * nkc * 4096;

    float acc[4][4][4];
#pragma unroll
    for (int i = 0; i < 4; i++)
#pragma unroll
        for (int j = 0; j < 4; j++)
#pragma unroll
            for (int l = 0; l < 4; l++) acc[i][j][l] = 0.f;

    auto stage_cp = [&](int s, int kc) {
        const float* ag = Ab + (size_t)kc * 4096;
        const float* bg = Bb + (size_t)kc * 4096;
        uint32_t sa = smb + (uint32_t)(s * STAGE_FLOATS) * 4;
        uint32_t sb = sa + AFRAG_FLOATS * 4;
#pragma unroll
        for (int p = 0; p < 4; p++) {
            int ch = tid + p * 256;
            int f = ch >> 5, off = ch & 31;
            cp16(sa + (uint32_t)(f * 528 + off * 16), ag + ch * 4);
        }
#pragma unroll
        for (int p = 0; p < 4; p++) {
            int ch = tid + p * 256;
            int fb = ch >> 4, off = ch & 15;
            cp16(sb + (uint32_t)(fb * 272 + off * 16), bg + ch * 4);
        }
    };

    const int niter = nkc;

    stage_cp(0, 0);
    asm volatile("cp.async.commit_group;");

    for (int it = 0; it < niter; it++) {
        const int s = it & 1;
        asm volatile("cp.async.wait_group 0;");
        __syncthreads();
        if (it + 1 < niter) {
            stage_cp(s ^ 1, it + 1);
            asm volatile("cp.async.commit_group;");
        }

        const float* as_ = sh + s * STAGE_FLOATS;
        const float* bs_ = as_ + AFRAG_FLOATS;

        uint32_t af[2][4][4], bf[2][4][2];

        auto ldfrag = [&](int ks, int buf) {
#pragma unroll
            for (int mf = 0; mf < 4; mf++) {
                float4 v = *reinterpret_cast<const float4*>(
                    as_ + ((wm * 4 + mf) * 4 + ks) * 132 + lane * 4);
                af[buf][mf][0] = __float_as_uint(v.x);
                af[buf][mf][1] = __float_as_uint(v.y);
                af[buf][mf][2] = __float_as_uint(v.z);
                af[buf][mf][3] = __float_as_uint(v.w);
            }
#pragma unroll
            for (int nf = 0; nf < 4; nf++) {
                float2 v = *reinterpret_cast<const float2*>(
                    bs_ + (ks * 16 + wn * 4 + nf) * 68 + lane * 2);
                bf[buf][nf][0] = __float_as_uint(v.x);
                bf[buf][nf][1] = __float_as_uint(v.y);
            }
        };

        ldfrag(0, 0);
#pragma unroll
        for (int ks = 0; ks < 4; ks++) {
            const int cur = ks & 1;
            if (ks < 3) ldfrag(ks + 1, cur ^ 1);
#pragma unroll
            for (int mf = 0; mf < 4; mf++)
#pragma unroll
                for (int nf = 0; nf < 4; nf++)
                    mma_tf32(acc[mf][nf], af[cur][mf], bf[cur][nf]);
        }
    }

    // epilogue: acc + bias -> C
    const int m0 = mb * 128;
    const int n0 = nb * 128;
#pragma unroll
    for (int mf = 0; mf < 4; mf++) {
        int r = m0 + wm * 64 + mf * 16 + g;
#pragma unroll
        for (int nf = 0; nf < 4; nf++) {
            int col = n0 + wn * 32 + nf * 8 + c * 2;
            float b0v = bias[col], b1v = bias[col + 1];
            *reinterpret_cast<float2*>(&C[(size_t)r * N + col]) =
                make_float2(acc[mf][nf][0] + b0v, acc[mf][nf][1] + b1v);
            *reinterpret_cast<float2*>(&C[(size_t)(r + 8) * N + col]) =
                make_float2(acc[mf][nf][2] + b0v, acc[mf][nf][3] + b1v);
        }
    }
}

// ===========================================================================
// Tensor-core flash attention — R12 structure, __expf -> fexp (FMA pipe).
// ===========================================================================
#define AT_BM 128
#define AT_BN 64
#define KSTR 132
#define VSTR 136
#define PSTR 68
#define SM_QF 0
#define SM_K0 16384
#define SM_K1 (16384 + 8448)
#define SM_V  (16384 + 16896)
#define SM_P  (16384 + 16896 + 8704)
#define AT_SMEM_FLOATS (16384 + 16896 + 8704 + 8704)
#define AT_SMEM_BYTES  (AT_SMEM_FLOATS * 4)

__global__ __launch_bounds__(256) void flash_attn_tc_kernel(
    const float* __restrict__ qkv, float* __restrict__ att)
{
    extern __shared__ float sm[];
    const int tid  = threadIdx.x;
    const int lane = tid & 31;
    const int w    = tid >> 5;
    const int g    = lane >> 2;
    const int c    = lane & 3;
    const int qb   = (int)gridDim.x - 1 - (int)blockIdx.x;
    const int h    = blockIdx.y;
    const int b    = blockIdx.z;
    const int q0   = qb * AT_BM;
    const size_t base = (size_t)b * SS_ * N_QKV + (size_t)h * HD;
    const float scale = 0.08838834764831845f;

    uint32_t smb;
    asm("{ .reg .u64 t; cvta.to.shared.u64 t, %1; cvt.u32.u64 %0, t; }" : "=r"(smb) : "l"(sm));

#pragma unroll
    for (int i = 0; i < 16; i++) {
        int id = tid + i * 256;
        int r  = id >> 5;
        int c4 = (id & 31) << 2;
        float4 v = *reinterpret_cast<const float4*>(&qkv[base + (size_t)(q0 + r) * N_QKV + c4]);
        int rb = r >> 4, rr = r & 15, gg = rr & 7, half = rr >> 3;
        int ks = c4 >> 3, khalf = (c4 >> 2) & 1;
        int reg = half + 2 * khalf;
        int ba = ((rb * 16 + ks) * 32) * 4 + reg;
        float vv[4] = {v.x, v.y, v.z, v.w};
#pragma unroll
        for (int j = 0; j < 4; j++)
            sm[SM_QF + ba + (gg * 4 + j) * 4] = __uint_as_float(f2tf(vv[j] * scale));
    }

    float o[16][4];
#pragma unroll
    for (int nt = 0; nt < 16; nt++)
#pragma unroll
        for (int l = 0; l < 4; l++) o[nt][l] = 0.f;
    float m0 = -INFINITY, m1 = -INFINITY, l0 = 0.f, l1 = 0.f;

    const int r0 = q0 + w * 16 + g;
    const int nkb = 2 * qb + 2;
    const uint32_t pbase = SM_P + w * (16 * PSTR);

#pragma unroll
    for (int i = 0; i < 8; i++) {
        int id = tid + i * 256;
        int row = id >> 5, c16 = (id & 31) << 2;
        cp16(smb + (uint32_t)(SM_K0 + row * KSTR + c16) * 4,
             &qkv[base + (size_t)row * N_QKV + DD + c16]);
    }
    asm volatile("cp.async.commit_group;");

    for (int kb = 0; kb < nkb; kb++) {
        const int k0 = kb * AT_BN;
        const int sK = (kb & 1) ? SM_K1 : SM_K0;

#pragma unroll
        for (int i = 0; i < 8; i++) {
            int id = tid + i * 256;
            int row = id >> 5, c16 = (id & 31) << 2;
            cp16(smb + (uint32_t)(SM_V + row * VSTR + c16) * 4,
                 &qkv[base + (size_t)(k0 + row) * N_QKV + 2 * DD + c16]);
        }
        asm volatile("cp.async.commit_group;");
        asm volatile("cp.async.wait_group 1;");
        __syncthreads();

        float s[8][4];
#pragma unroll
        for (int nt = 0; nt < 8; nt++)
#pragma unroll
            for (int l = 0; l < 4; l++) s[nt][l] = 0.f;

#pragma unroll
        for (int ks = 0; ks < 16; ks++) {
            float4 qa = *reinterpret_cast<const float4*>(&sm[SM_QF + ((w * 16 + ks) * 32 + lane) * 4]);
            uint32_t a[4] = {__float_as_uint(qa.x), __float_as_uint(qa.y),
                             __float_as_uint(qa.z), __float_as_uint(qa.w)};
#pragma unroll
            for (int nt = 0; nt < 8; nt++) {
                const float* kp = &sm[sK + (nt * 8 + g) * KSTR + ks * 8 + c];
                uint32_t bfr[2] = {f2tf(kp[0]), f2tf(kp[4])};
                mma_tf32(s[nt], a, bfr);
            }
        }

        if (kb + 1 < nkb) {
            const int sKn = (kb & 1) ? SM_K0 : SM_K1;
            const int k0n = (kb + 1) * AT_BN;
#pragma unroll
            for (int i = 0; i < 8; i++) {
                int id = tid + i * 256;
                int row = id >> 5, c16 = (id & 31) << 2;
                cp16(smb + (uint32_t)(sKn + row * KSTR + c16) * 4,
                     &qkv[base + (size_t)(k0n + row) * N_QKV + DD + c16]);
            }
        }
        asm volatile("cp.async.commit_group;");

        if (k0 + 63 > q0 + w * 16) {
#pragma unroll
            for (int nt = 0; nt < 8; nt++) {
                int col = k0 + nt * 8 + 2 * c;
                if (col     > r0)     s[nt][0] = -INFINITY;
                if (col + 1 > r0)     s[nt][1] = -INFINITY;
                if (col     > r0 + 8) s[nt][2] = -INFINITY;
                if (col + 1 > r0 + 8) s[nt][3] = -INFINITY;
            }
        }

        float mt0 = -INFINITY, mt1 = -INFINITY;
#pragma unroll
        for (int nt = 0; nt < 8; nt++) {
            mt0 = fmaxf(mt0, fmaxf(s[nt][0], s[nt][1]));
            mt1 = fmaxf(mt1, fmaxf(s[nt][2], s[nt][3]));
        }
        mt0 = fmaxf(mt0, __shfl_xor_sync(0xffffffffu, mt0, 1));
        mt0 = fmaxf(mt0, __shfl_xor_sync(0xffffffffu, mt0, 2));
        mt1 = fmaxf(mt1, __shfl_xor_sync(0xffffffffu, mt1, 1));
        mt1 = fmaxf(mt1, __shfl_xor_sync(0xffffffffu, mt1, 2));

        float mn0 = fmaxf(m0, mt0), mn1 = fmaxf(m1, mt1);
        float cr0 = fexp(m0 - mn0), cr1 = fexp(m1 - mn1);
        m0 = mn0; m1 = mn1;

        float ps0 = 0.f, ps1 = 0.f;
#pragma unroll
        for (int nt = 0; nt < 8; nt++) {
            float p00 = fexp(s[nt][0] - m0);
            float p01 = fexp(s[nt][1] - m0);
            float p10 = fexp(s[nt][2] - m1);
            float p11 = fexp(s[nt][3] - m1);
            ps0 += p00 + p01;
            ps1 += p10 + p11;
            uint2 u0 = make_uint2(f2tf(p00), f2tf(p01));
            uint2 u1 = make_uint2(f2tf(p10), f2tf(p11));
            *reinterpret_cast<uint2*>(&sm[pbase + g * PSTR + nt * 8 + 2 * c])       = u0;
            *reinterpret_cast<uint2*>(&sm[pbase + (g + 8) * PSTR + nt * 8 + 2 * c]) = u1;
        }
        ps0 += __shfl_xor_sync(0xffffffffu, ps0, 1);
        ps0 += __shfl_xor_sync(0xffffffffu, ps0, 2);
        ps1 += __shfl_xor_sync(0xffffffffu, ps1, 1);
        ps1 += __shfl_xor_sync(0xffffffffu, ps1, 2);
        l0 = l0 * cr0 + ps0;
        l1 = l1 * cr1 + ps1;

#pragma unroll
        for (int nt = 0; nt < 16; nt++) {
            o[nt][0] *= cr0; o[nt][1] *= cr0;
            o[nt][2] *= cr1; o[nt][3] *= cr1;
        }

        asm volatile("cp.async.wait_group 1;");
        __syncthreads();

#pragma unroll
        for (int ks2 = 0; ks2 < 8; ks2++) {
            uint32_t a[4];
            a[0] = __float_as_uint(sm[pbase + g * PSTR + ks2 * 8 + c]);
            a[1] = __float_as_uint(sm[pbase + (g + 8) * PSTR + ks2 * 8 + c]);
            a[2] = __float_as_uint(sm[pbase + g * PSTR + ks2 * 8 + c + 4]);
            a[3] = __float_as_uint(sm[pbase + (g + 8) * PSTR + ks2 * 8 + c + 4]);
#pragma unroll
            for (int nt = 0; nt < 16; nt++) {
                uint32_t bfr[2] = {
                    __float_as_uint(sm[SM_V + (ks2 * 8 + c) * VSTR + nt * 8 + g]),
                    __float_as_uint(sm[SM_V + (ks2 * 8 + c + 4) * VSTR + nt * 8 + g])};
                mma_tf32(o[nt], a, bfr);
            }
        }
        __syncthreads();
    }

    float il0 = 1.f / l0, il1 = 1.f / l1;
    size_t ob = ((size_t)(b * SS_) + q0 + w * 16) * DD + (size_t)h * HD;
#pragma unroll
    for (int nt = 0; nt < 16; nt++) {
        int col = nt * 8 + 2 * c;
        uint2 w0 = make_uint2(f2tf(o[nt][0] * il0), f2tf(o[nt][1] * il0));
        uint2 w1 = make_uint2(f2tf(o[nt][2] * il1), f2tf(o[nt][3] * il1));
        *reinterpret_cast<uint2*>(&att[ob + (size_t)g * DD + col])       = w0;
        *reinterpret_cast<uint2*>(&att[ob + (size_t)(g + 8) * DD + col]) = w1;
    }
}

// ===========================================================================
// Launch
// ===========================================================================
extern "C" void kernel_launch(void* const* d_in, const int* in_sizes, int n_in,
                              void* d_out, int out_size)
{
    const float* x      = (const float*)d_in[0];
    const float* W_qkv  = (const float*)d_in[1];
    const float* b_qkv  = (const float*)d_in[2];
    const float* W_out  = (const float*)d_in[3];
    const float* b_out  = (const float*)d_in[4];
    float* out          = (float*)d_out;

    float *qkv_p, *att_p, *xfm_p, *attfm_p, *w1fm_p, *w2fm_p;
    cudaGetSymbolAddress((void**)&qkv_p,   g_qkv);
    cudaGetSymbolAddress((void**)&att_p,   g_att);
    cudaGetSymbolAddress((void**)&xfm_p,   g_xfm);
    cudaGetSymbolAddress((void**)&attfm_p, g_attfm);
    cudaGetSymbolAddress((void**)&w1fm_p,  g_w1fm);
    cudaGetSymbolAddress((void**)&w2fm_p,  g_w2fm);

    cudaFuncSetAttribute(gemm_fm_kernel,
                         cudaFuncAttributeMaxDynamicSharedMemorySize, GEMM_SMEM_BYTES);
    cudaFuncSetAttribute(flash_attn_tc_kernel,
                         cudaFuncAttributeMaxDynamicSharedMemorySize, AT_SMEM_BYTES);

    // One-time operand formatting (rounds to tf32 + fragment-major layout)
    prep_a_kernel<<<(M_TOT / 128) * (DD / 32), 256>>>(x, xfm_p, DD);
    prep_b_kernel<<<(N_QKV / 128) * (DD / 32), 256>>>(W_qkv, w1fm_p, N_QKV, DD);
    prep_b_kernel<<<(DD / 128) * (DD / 32), 256>>>(W_out, w2fm_p, DD, DD);

    // QKV projection: [4096,2048] @ [2048,6144]
    gemm_fm_kernel<<<dim3(N_QKV / 128, M_TOT / 128), 256, GEMM_SMEM_BYTES>>>(
        xfm_p, w1fm_p, b_qkv, qkv_p, M_TOT, N_QKV, DD);

    // Fused causal attention (tensor-core)
    flash_attn_tc_kernel<<<dim3(SS_ / AT_BM, HH, BB), 256, AT_SMEM_BYTES>>>(qkv_p, att_p);

    // Format attention output as A for the out-projection
    prep_a_kernel<<<(M_TOT / 128) * (DD / 32), 256>>>(att_p, attfm_p, DD);

    // Output projection: [4096,2048] @ [2048,2048]
    gemm_fm_kernel<<<dim3(DD / 128, M_TOT / 128), 256, GEMM_SMEM_BYTES>>>(
        attfm_p, w2fm_p, b_out, out, M_TOT, DD, DD);
}

// round 14
// speedup vs baseline: 1.0612x; 1.0612x over previous
#include <cuda_runtime.h>
#include <math.h>
#include <stdint.h>

#define BB 2
#define SS_ 2048
#define DD 2048
#define HH 16
#define HD 128
#define M_TOT (BB * SS_)     // 4096
#define N_QKV (3 * DD)       // 6144

__device__ float g_qkv[M_TOT * N_QKV];     // qkv rows (tf32-rounded by gemm epilogue)
__device__ float g_att[M_TOT * DD];        // attention out rows (tf32-rounded)
__device__ float g_xfm [M_TOT * DD];       // x, fragment-major A
__device__ float g_attfm[M_TOT * DD];      // att, fragment-major A
__device__ float g_w1fm[DD * N_QKV];       // W_qkv, fragment-major B
__device__ float g_w2fm[DD * DD];          // W_out, fragment-major B

__device__ __forceinline__ uint32_t f2tf(float f) {
    uint32_t u;
    asm("cvt.rna.tf32.f32 %0, %1;" : "=r"(u) : "f"(f));
    return u;
}

// FMA-pipe exp: exp(x) = 2^(x*log2e), magic-number split, degree-5 poly.
__device__ __forceinline__ float fexp(float x) {
    x = fmaxf(x, -87.0f);
    const float L2E = 1.4426950408889634f;
    float y  = fmaf(x, L2E, 12582912.0f);
    int   ni = __float_as_int(y);
    float nf = y - 12582912.0f;
    float f  = fmaf(x, L2E, -nf);
    float p  = 0.00133335581f;
    p = fmaf(p, f, 0.00961812911f);
    p = fmaf(p, f, 0.0555041087f);
    p = fmaf(p, f, 0.240226507f);
    p = fmaf(p, f, 0.693147180f);
    p = fmaf(p, f, 1.0f);
    float scale = __int_as_float((ni - 0x4B400000 + 127) << 23);
    return scale * p;
}

__device__ __forceinline__ void mma_tf32(float* d, const uint32_t* a, const uint32_t* b) {
    asm volatile(
        "mma.sync.aligned.m16n8k8.row.col.f32.tf32.tf32.f32 "
        "{%0,%1,%2,%3}, {%4,%5,%6,%7}, {%8,%9}, {%0,%1,%2,%3};\n"
        : "+f"(d[0]), "+f"(d[1]), "+f"(d[2]), "+f"(d[3])
        : "r"(a[0]), "r"(a[1]), "r"(a[2]), "r"(a[3]), "r"(b[0]), "r"(b[1]));
}

__device__ __forceinline__ void cp16(uint32_t saddr, const float* gptr) {
    asm volatile("cp.async.cg.shared.global [%0], [%1], 16;" :: "r"(saddr), "l"(gptr));
}

// ===========================================================================
// Prep A: row-major [M,K] fp32 -> fragment-major tf32 blocks (as R12).
// ===========================================================================
__global__ __launch_bounds__(256) void prep_a_kernel(
    const float* __restrict__ src, float* __restrict__ dst, int K)
{
    __shared__ float tile[128 * 36];
    const int tid = threadIdx.x;
    const int nkc = K >> 5;
    const int mb = blockIdx.x / nkc;
    const int kc = blockIdx.x % nkc;
    const float* s0 = src + (size_t)mb * 128 * K + kc * 32;

#pragma unroll
    for (int p = 0; p < 4; p++) {
        int id = tid + p * 256;
        int row = id >> 3, c4 = (id & 7) << 2;
        float4 v = *reinterpret_cast<const float4*>(s0 + (size_t)row * K + c4);
        float* t = &tile[row * 36 + c4];
        t[0] = v.x; t[1] = v.y; t[2] = v.z; t[3] = v.w;
    }
    __syncthreads();

    float* d0 = dst + (size_t)blockIdx.x * 4096;
#pragma unroll
    for (int p = 0; p < 4; p++) {
        int q = tid + p * 256;
        int f = q >> 5;
        int l = q & 31;
        int g = l >> 2, c = l & 3;
        int mf = f >> 2, ks = f & 3;
        const float* tl = &tile[(mf * 16 + g) * 36 + ks * 8 + c];
        uint4 o;
        o.x = f2tf(tl[0]);
        o.y = f2tf(tl[8 * 36]);
        o.z = f2tf(tl[4]);
        o.w = f2tf(tl[8 * 36 + 4]);
        *reinterpret_cast<uint4*>(d0 + q * 4) = o;
    }
}

// ===========================================================================
// Prep B: row-major W[K,N] fp32 -> fragment-major tf32 blocks (as R12).
// ===========================================================================
__global__ __launch_bounds__(256) void prep_b_kernel(
    const float* __restrict__ src, float* __restrict__ dst, int N, int K)
{
    __shared__ float tile[32 * 132];
    const int tid = threadIdx.x;
    const int nkc = K >> 5;
    const int nb = blockIdx.x / nkc;
    const int kc = blockIdx.x % nkc;
    const float* s0 = src + (size_t)(kc * 32) * N + nb * 128;

#pragma unroll
    for (int p = 0; p < 4; p++) {
        int id = tid + p * 256;
        int k = id >> 5, n4 = (id & 31) << 2;
        float4 v = *reinterpret_cast<const float4*>(s0 + (size_t)k * N + n4);
        *reinterpret_cast<float4*>(&tile[k * 132 + n4]) = v;
    }
    __syncthreads();

    float* d0 = dst + (size_t)blockIdx.x * 4096;
#pragma unroll
    for (int p = 0; p < 4; p++) {
        int q = tid + p * 256;
        int fb = q >> 4;
        int ks = fb >> 4, n8 = fb & 15;
        int o4 = (q & 15) << 2;
        uint4 o;
        uint32_t* ov = reinterpret_cast<uint32_t*>(&o);
#pragma unroll
        for (int i = 0; i < 4; i++) {
            int off = o4 + i;
            int g = off >> 3, c = (off & 7) >> 1, u = off & 1;
            ov[i] = f2tf(tile[(ks * 8 + u * 4 + c) * 132 + n8 * 8 + g]);
        }
        *reinterpret_cast<uint4*>(d0 + q * 4) = o;
    }
}

// ===========================================================================
// TF32 mma.sync GEMM — exact R12 structure (96 regs, 2 CTAs/SM, tensor 59.7%).
// round_out=1: epilogue stores tf32-rounded values (for qkv -> attention).
// ===========================================================================
#define AFRAG_FLOATS 4224                 // 32 frags * 132  (528 B, 16-aligned)
#define BFRAG_FLOATS 4352                 // 64 frags * 68   (272 B, 16-aligned)
#define STAGE_FLOATS (AFRAG_FLOATS + BFRAG_FLOATS)
#define GEMM_SMEM_BYTES (2 * STAGE_FLOATS * 4)   // 68608

__global__ __launch_bounds__(256) void gemm_fm_kernel(
    const float* __restrict__ Afm, const float* __restrict__ Bfm,
    const float* __restrict__ bias, float* __restrict__ C,
    int M, int N, int K, int round_out)
{
    extern __shared__ float sh[];
    uint32_t smb;
    asm("{ .reg .u64 t; cvta.to.shared.u64 t, %1; cvt.u32.u64 %0, t; }"
        : "=r"(smb) : "l"(sh));

    const int tid  = threadIdx.x;
    const int lane = tid & 31;
    const int wid  = tid >> 5;
    const int wm   = wid & 1;
    const int wn   = wid >> 1;
    const int g    = lane >> 2;
    const int c    = lane & 3;

    const int nkc = K >> 5;
    const int mb  = blockIdx.y;
    const int nb  = blockIdx.x;
    const float* Ab = Afm + (size_t)mb * nkc * 4096;
    const float* Bb = Bfm + (size_t)nb * nkc * 4096;

    float acc[4][4][4];
#pragma unroll
    for (int i = 0; i < 4; i++)
#pragma unroll
        for (int j = 0; j < 4; j++)
#pragma unroll
            for (int l = 0; l < 4; l++) acc[i][j][l] = 0.f;

    auto stage_cp = [&](int s, int kc) {
        const float* ag = Ab + (size_t)kc * 4096;
        const float* bg = Bb + (size_t)kc * 4096;
        uint32_t sa = smb + (uint32_t)(s * STAGE_FLOATS) * 4;
        uint32_t sb = sa + AFRAG_FLOATS * 4;
#pragma unroll
        for (int p = 0; p < 4; p++) {
            int ch = tid + p * 256;
            int f = ch >> 5, off = ch & 31;
            cp16(sa + (uint32_t)(f * 528 + off * 16), ag + ch * 4);
        }
#pragma unroll
        for (int p = 0; p < 4; p++) {
            int ch = tid + p * 256;
            int fb = ch >> 4, off = ch & 15;
            cp16(sb + (uint32_t)(fb * 272 + off * 16), bg + ch * 4);
        }
    };

    auto compute = [&](int s, int ks) {
        const float* as_ = sh + s * STAGE_FLOATS;
        const float* bs_ = as_ + AFRAG_FLOATS;
        uint32_t af[4][4], bfr[4][2];
#pragma unroll
        for (int mf = 0; mf < 4; mf++) {
            float4 v = *reinterpret_cast<const float4*>(
                as_ + ((wm * 4 + mf) * 4 + ks) * 132 + lane * 4);
            af[mf][0] = __float_as_uint(v.x);
            af[mf][1] = __float_as_uint(v.y);
            af[mf][2] = __float_as_uint(v.z);
            af[mf][3] = __float_as_uint(v.w);
        }
#pragma unroll
        for (int nf = 0; nf < 4; nf++) {
            float2 v = *reinterpret_cast<const float2*>(
                bs_ + (ks * 16 + wn * 4 + nf) * 68 + lane * 2);
            bfr[nf][0] = __float_as_uint(v.x);
            bfr[nf][1] = __float_as_uint(v.y);
        }
#pragma unroll
        for (int mf = 0; mf < 4; mf++)
#pragma unroll
            for (int nf = 0; nf < 4; nf++)
                mma_tf32(acc[mf][nf], af[mf], bfr[nf]);
    };

    const int niter = nkc;

    stage_cp(0, 0);
    asm volatile("cp.async.commit_group;");

    for (int it = 0; it < niter; it++) {
        const int s = it & 1;
        asm volatile("cp.async.wait_group 0;");
        __syncthreads();
        if (it + 1 < niter) {
            stage_cp(s ^ 1, it + 1);
            asm volatile("cp.async.commit_group;");
        }
        compute(s, 0);
        compute(s, 1);
        compute(s, 2);
        compute(s, 3);
    }

    // epilogue: acc + bias -> C (optionally tf32-rounded)
    const int m0 = mb * 128;
    const int n0 = nb * 128;
#pragma unroll
    for (int mf = 0; mf < 4; mf++) {
        int r = m0 + wm * 64 + mf * 16 + g;
#pragma unroll
        for (int nf = 0; nf < 4; nf++) {
            int col = n0 + wn * 32 + nf * 8 + c * 2;
            float b0v = bias[col], b1v = bias[col + 1];
            float v00 = acc[mf][nf][0] + b0v, v01 = acc[mf][nf][1] + b1v;
            float v10 = acc[mf][nf][2] + b0v, v11 = acc[mf][nf][3] + b1v;
            if (round_out) {
                v00 = __uint_as_float(f2tf(v00));
                v01 = __uint_as_float(f2tf(v01));
                v10 = __uint_as_float(f2tf(v10));
                v11 = __uint_as_float(f2tf(v11));
            }
            *reinterpret_cast<float2*>(&C[(size_t)r * N + col])       = make_float2(v00, v01);
            *reinterpret_cast<float2*>(&C[(size_t)(r + 8) * N + col]) = make_float2(v10, v11);
        }
    }
}

// ===========================================================================
// Tensor-core flash attention. qkv is pre-rounded tf32 -> K and V fragments
// are plain loads (no cvt in QK mainloop). fexp for softmax (FMA pipe).
// ===========================================================================
#define AT_BM 128
#define AT_BN 64
#define KSTR 132
#define VSTR 136
#define PSTR 68
#define SM_QF 0
#define SM_K0 16384
#define SM_K1 (16384 + 8448)
#define SM_V  (16384 + 16896)
#define SM_P  (16384 + 16896 + 8704)
#define AT_SMEM_FLOATS (16384 + 16896 + 8704 + 8704)
#define AT_SMEM_BYTES  (AT_SMEM_FLOATS * 4)

__global__ __launch_bounds__(256) void flash_attn_tc_kernel(
    const float* __restrict__ qkv, float* __restrict__ att)
{
    extern __shared__ float sm[];
    const int tid  = threadIdx.x;
    const int lane = tid & 31;
    const int w    = tid >> 5;
    const int g    = lane >> 2;
    const int c    = lane & 3;
    const int qb   = (int)gridDim.x - 1 - (int)blockIdx.x;
    const int h    = blockIdx.y;
    const int b    = blockIdx.z;
    const int q0   = qb * AT_BM;
    const size_t base = (size_t)b * SS_ * N_QKV + (size_t)h * HD;
    const float scale = 0.08838834764831845f;

    uint32_t smb;
    asm("{ .reg .u64 t; cvta.to.shared.u64 t, %1; cvt.u32.u64 %0, t; }" : "=r"(smb) : "l"(sm));

#pragma unroll
    for (int i = 0; i < 16; i++) {
        int id = tid + i * 256;
        int r  = id >> 5;
        int c4 = (id & 31) << 2;
        float4 v = *reinterpret_cast<const float4*>(&qkv[base + (size_t)(q0 + r) * N_QKV + c4]);
        int rb = r >> 4, rr = r & 15, gg = rr & 7, half = rr >> 3;
        int ks = c4 >> 3, khalf = (c4 >> 2) & 1;
        int reg = half + 2 * khalf;
        int ba = ((rb * 16 + ks) * 32) * 4 + reg;
        float vv[4] = {v.x, v.y, v.z, v.w};
#pragma unroll
        for (int j = 0; j < 4; j++)
            sm[SM_QF + ba + (gg * 4 + j) * 4] = __uint_as_float(f2tf(vv[j] * scale));
    }

    float o[16][4];
#pragma unroll
    for (int nt = 0; nt < 16; nt++)
#pragma unroll
        for (int l = 0; l < 4; l++) o[nt][l] = 0.f;
    float m0 = -INFINITY, m1 = -INFINITY, l0 = 0.f, l1 = 0.f;

    const int r0 = q0 + w * 16 + g;
    const int nkb = 2 * qb + 2;
    const uint32_t pbase = SM_P + w * (16 * PSTR);

#pragma unroll
    for (int i = 0; i < 8; i++) {
        int id = tid + i * 256;
        int row = id >> 5, c16 = (id & 31) << 2;
        cp16(smb + (uint32_t)(SM_K0 + row * KSTR + c16) * 4,
             &qkv[base + (size_t)row * N_QKV + DD + c16]);
    }
    asm volatile("cp.async.commit_group;");

    for (int kb = 0; kb < nkb; kb++) {
        const int k0 = kb * AT_BN;
        const int sK = (kb & 1) ? SM_K1 : SM_K0;

#pragma unroll
        for (int i = 0; i < 8; i++) {
            int id = tid + i * 256;
            int row = id >> 5, c16 = (id & 31) << 2;
            cp16(smb + (uint32_t)(SM_V + row * VSTR + c16) * 4,
                 &qkv[base + (size_t)(k0 + row) * N_QKV + 2 * DD + c16]);
        }
        asm volatile("cp.async.commit_group;");
        asm volatile("cp.async.wait_group 1;");
        __syncthreads();

        float s[8][4];
#pragma unroll
        for (int nt = 0; nt < 8; nt++)
#pragma unroll
            for (int l = 0; l < 4; l++) s[nt][l] = 0.f;

#pragma unroll
        for (int ks = 0; ks < 16; ks++) {
            float4 qa = *reinterpret_cast<const float4*>(&sm[SM_QF + ((w * 16 + ks) * 32 + lane) * 4]);
            uint32_t a[4] = {__float_as_uint(qa.x), __float_as_uint(qa.y),
                             __float_as_uint(qa.z), __float_as_uint(qa.w)};
#pragma unroll
            for (int nt = 0; nt < 8; nt++) {
                const float* kp = &sm[sK + (nt * 8 + g) * KSTR + ks * 8 + c];
                uint32_t bfr[2] = {__float_as_uint(kp[0]), __float_as_uint(kp[4])};
                mma_tf32(s[nt], a, bfr);
            }
        }

        if (kb + 1 < nkb) {
            const int sKn = (kb & 1) ? SM_K0 : SM_K1;
            const int k0n = (kb + 1) * AT_BN;
#pragma unroll
            for (int i = 0; i < 8; i++) {
                int id = tid + i * 256;
                int row = id >> 5, c16 = (id & 31) << 2;
                cp16(smb + (uint32_t)(sKn + row * KSTR + c16) * 4,
                     &qkv[base + (size_t)(k0n + row) * N_QKV + DD + c16]);
            }
        }
        asm volatile("cp.async.commit_group;");

        if (k0 + 63 > q0 + w * 16) {
#pragma unroll
            for (int nt = 0; nt < 8; nt++) {
                int col = k0 + nt * 8 + 2 * c;
                if (col     > r0)     s[nt][0] = -INFINITY;
                if (col + 1 > r0)     s[nt][1] = -INFINITY;
                if (col     > r0 + 8) s[nt][2] = -INFINITY;
                if (col + 1 > r0 + 8) s[nt][3] = -INFINITY;
            }
        }

        float mt0 = -INFINITY, mt1 = -INFINITY;
#pragma unroll
        for (int nt = 0; nt < 8; nt++) {
            mt0 = fmaxf(mt0, fmaxf(s[nt][0], s[nt][1]));
            mt1 = fmaxf(mt1, fmaxf(s[nt][2], s[nt][3]));
        }
        mt0 = fmaxf(mt0, __shfl_xor_sync(0xffffffffu, mt0, 1));
        mt0 = fmaxf(mt0, __shfl_xor_sync(0xffffffffu, mt0, 2));
        mt1 = fmaxf(mt1, __shfl_xor_sync(0xffffffffu, mt1, 1));
        mt1 = fmaxf(mt1, __shfl_xor_sync(0xffffffffu, mt1, 2));

        float mn0 = fmaxf(m0, mt0), mn1 = fmaxf(m1, mt1);
        float cr0 = fexp(m0 - mn0), cr1 = fexp(m1 - mn1);
        m0 = mn0; m1 = mn1;

        float ps0 = 0.f, ps1 = 0.f;
#pragma unroll
        for (int nt = 0; nt < 8; nt++) {
            float p00 = fexp(s[nt][0] - m0);
            float p01 = fexp(s[nt][1] - m0);
            float p10 = fexp(s[nt][2] - m1);
            float p11 = fexp(s[nt][3] - m1);
            ps0 += p00 + p01;
            ps1 += p10 + p11;
            uint2 u0 = make_uint2(f2tf(p00), f2tf(p01));
            uint2 u1 = make_uint2(f2tf(p10), f2tf(p11));
            *reinterpret_cast<uint2*>(&sm[pbase + g * PSTR + nt * 8 + 2 * c])       = u0;
            *reinterpret_cast<uint2*>(&sm[pbase + (g + 8) * PSTR + nt * 8 + 2 * c]) = u1;
        }
        ps0 += __shfl_xor_sync(0xffffffffu, ps0, 1);
        ps0 += __shfl_xor_sync(0xffffffffu, ps0, 2);
        ps1 += __shfl_xor_sync(0xffffffffu, ps1, 1);
        ps1 += __shfl_xor_sync(0xffffffffu, ps1, 2);
        l0 = l0 * cr0 + ps0;
        l1 = l1 * cr1 + ps1;

#pragma unroll
        for (int nt = 0; nt < 16; nt++) {
            o[nt][0] *= cr0; o[nt][1] *= cr0;
            o[nt][2] *= cr1; o[nt][3] *= cr1;
        }

        asm volatile("cp.async.wait_group 1;");
        __syncthreads();

#pragma unroll
        for (int ks2 = 0; ks2 < 8; ks2++) {
            uint32_t a[4];
            a[0] = __float_as_uint(sm[pbase + g * PSTR + ks2 * 8 + c]);
            a[1] = __float_as_uint(sm[pbase + (g + 8) * PSTR + ks2 * 8 + c]);
            a[2] = __float_as_uint(sm[pbase + g * PSTR + ks2 * 8 + c + 4]);
            a[3] = __float_as_uint(sm[pbase + (g + 8) * PSTR + ks2 * 8 + c + 4]);
#pragma unroll
            for (int nt = 0; nt < 16; nt++) {
                uint32_t bfr[2] = {
                    __float_as_uint(sm[SM_V + (ks2 * 8 + c) * VSTR + nt * 8 + g]),
                    __float_as_uint(sm[SM_V + (ks2 * 8 + c + 4) * VSTR + nt * 8 + g])};
                mma_tf32(o[nt], a, bfr);
            }
        }
        __syncthreads();
    }

    float il0 = 1.f / l0, il1 = 1.f / l1;
    size_t ob = ((size_t)(b * SS_) + q0 + w * 16) * DD + (size_t)h * HD;
#pragma unroll
    for (int nt = 0; nt < 16; nt++) {
        int col = nt * 8 + 2 * c;
        uint2 w0 = make_uint2(f2tf(o[nt][0] * il0), f2tf(o[nt][1] * il0));
        uint2 w1 = make_uint2(f2tf(o[nt][2] * il1), f2tf(o[nt][3] * il1));
        *reinterpret_cast<uint2*>(&att[ob + (size_t)g * DD + col])       = w0;
        *reinterpret_cast<uint2*>(&att[ob + (size_t)(g + 8) * DD + col]) = w1;
    }
}

// ===========================================================================
// Launch
// ===========================================================================
extern "C" void kernel_launch(void* const* d_in, const int* in_sizes, int n_in,
                              void* d_out, int out_size)
{
    const float* x      = (const float*)d_in[0];
    const float* W_qkv  = (const float*)d_in[1];
    const float* b_qkv  = (const float*)d_in[2];
    const float* W_out  = (const float*)d_in[3];
    const float* b_out  = (const float*)d_in[4];
    float* out          = (float*)d_out;

    float *qkv_p, *att_p, *xfm_p, *attfm_p, *w1fm_p, *w2fm_p;
    cudaGetSymbolAddress((void**)&qkv_p,   g_qkv);
    cudaGetSymbolAddress((void**)&att_p,   g_att);
    cudaGetSymbolAddress((void**)&xfm_p,   g_xfm);
    cudaGetSymbolAddress((void**)&attfm_p, g_attfm);
    cudaGetSymbolAddress((void**)&w1fm_p,  g_w1fm);
    cudaGetSymbolAddress((void**)&w2fm_p,  g_w2fm);

    cudaFuncSetAttribute(gemm_fm_kernel,
                         cudaFuncAttributeMaxDynamicSharedMemorySize, GEMM_SMEM_BYTES);
    cudaFuncSetAttribute(flash_attn_tc_kernel,
                         cudaFuncAttributeMaxDynamicSharedMemorySize, AT_SMEM_BYTES);

    // One-time operand formatting (rounds to tf32 + fragment-major layout)
    prep_a_kernel<<<(M_TOT / 128) * (DD / 32), 256>>>(x, xfm_p, DD);
    prep_b_kernel<<<(N_QKV / 128) * (DD / 32), 256>>>(W_qkv, w1fm_p, N_QKV, DD);
    prep_b_kernel<<<(DD / 128) * (DD / 32), 256>>>(W_out, w2fm_p, DD, DD);

    // QKV projection (tf32-rounded output so attention skips cvt on K/V)
    gemm_fm_kernel<<<dim3(N_QKV / 128, M_TOT / 128), 256, GEMM_SMEM_BYTES>>>(
        xfm_p, w1fm_p, b_qkv, qkv_p, M_TOT, N_QKV, DD, 1);

    // Fused causal attention (tensor-core)
    flash_attn_tc_kernel<<<dim3(SS_ / AT_BM, HH, BB), 256, AT_SMEM_BYTES>>>(qkv_p, att_p);

    // Format attention output as A for the out-projection
    prep_a_kernel<<<(M_TOT / 128) * (DD / 32), 256>>>(att_p, attfm_p, DD);

    // Output projection (raw fp32 output — final answer)
    gemm_fm_kernel<<<dim3(DD / 128, M_TOT / 128), 256, GEMM_SMEM_BYTES>>>(
        attfm_p, w2fm_p, b_out, out, M_TOT, DD, DD, 0);
}

// round 15
// speedup vs baseline: 1.0676x; 1.0060x over previous
#include <cuda_runtime.h>
#include <math.h>
#include <stdint.h>

#define BB 2
#define SS_ 2048
#define DD 2048
#define HH 16
#define HD 128
#define M_TOT (BB * SS_)     // 4096
#define N_QKV (3 * DD)       // 6144

__device__ float g_qkv[M_TOT * N_QKV];     // qkv rows (tf32-rounded by gemm epilogue)
__device__ float g_att[M_TOT * DD];        // attention out rows (tf32-rounded)
__device__ float g_xfm [M_TOT * DD];       // x, fragment-major A
__device__ float g_attfm[M_TOT * DD];      // att, fragment-major A
__device__ float g_w1fm[DD * N_QKV];       // W_qkv, fragment-major B
__device__ float g_w2fm[DD * DD];          // W_out, fragment-major B

__device__ __forceinline__ uint32_t f2tf(float f) {
    uint32_t u;
    asm("cvt.rna.tf32.f32 %0, %1;" : "=r"(u) : "f"(f));
    return u;
}

// FMA-pipe exp: exp(x) = 2^(x*log2e), magic-number split, degree-5 poly.
__device__ __forceinline__ float fexp(float x) {
    x = fmaxf(x, -87.0f);
    const float L2E = 1.4426950408889634f;
    float y  = fmaf(x, L2E, 12582912.0f);
    int   ni = __float_as_int(y);
    float nf = y - 12582912.0f;
    float f  = fmaf(x, L2E, -nf);
    float p  = 0.00133335581f;
    p = fmaf(p, f, 0.00961812911f);
    p = fmaf(p, f, 0.0555041087f);
    p = fmaf(p, f, 0.240226507f);
    p = fmaf(p, f, 0.693147180f);
    p = fmaf(p, f, 1.0f);
    float scale = __int_as_float((ni - 0x4B400000 + 127) << 23);
    return scale * p;
}

__device__ __forceinline__ void mma_tf32(float* d, const uint32_t* a, const uint32_t* b) {
    asm volatile(
        "mma.sync.aligned.m16n8k8.row.col.f32.tf32.tf32.f32 "
        "{%0,%1,%2,%3}, {%4,%5,%6,%7}, {%8,%9}, {%0,%1,%2,%3};\n"
        : "+f"(d[0]), "+f"(d[1]), "+f"(d[2]), "+f"(d[3])
        : "r"(a[0]), "r"(a[1]), "r"(a[2]), "r"(a[3]), "r"(b[0]), "r"(b[1]));
}

__device__ __forceinline__ void cp16(uint32_t saddr, const float* gptr) {
    asm volatile("cp.async.cg.shared.global [%0], [%1], 16;" :: "r"(saddr), "l"(gptr));
}

// ===========================================================================
// Prep A: row-major [M,K] fp32 -> fragment-major tf32 blocks (as R12).
// ===========================================================================
__global__ __launch_bounds__(256) void prep_a_kernel(
    const float* __restrict__ src, float* __restrict__ dst, int K)
{
    __shared__ float tile[128 * 36];
    const int tid = threadIdx.x;
    const int nkc = K >> 5;
    const int mb = blockIdx.x / nkc;
    const int kc = blockIdx.x % nkc;
    const float* s0 = src + (size_t)mb * 128 * K + kc * 32;

#pragma unroll
    for (int p = 0; p < 4; p++) {
        int id = tid + p * 256;
        int row = id >> 3, c4 = (id & 7) << 2;
        float4 v = *reinterpret_cast<const float4*>(s0 + (size_t)row * K + c4);
        float* t = &tile[row * 36 + c4];
        t[0] = v.x; t[1] = v.y; t[2] = v.z; t[3] = v.w;
    }
    __syncthreads();

    float* d0 = dst + (size_t)blockIdx.x * 4096;
#pragma unroll
    for (int p = 0; p < 4; p++) {
        int q = tid + p * 256;
        int f = q >> 5;
        int l = q & 31;
        int g = l >> 2, c = l & 3;
        int mf = f >> 2, ks = f & 3;
        const float* tl = &tile[(mf * 16 + g) * 36 + ks * 8 + c];
        uint4 o;
        o.x = f2tf(tl[0]);
        o.y = f2tf(tl[8 * 36]);
        o.z = f2tf(tl[4]);
        o.w = f2tf(tl[8 * 36 + 4]);
        *reinterpret_cast<uint4*>(d0 + q * 4) = o;
    }
}

// ===========================================================================
// Prep B: row-major W[K,N] fp32 -> fragment-major tf32 blocks (as R12).
// ===========================================================================
__global__ __launch_bounds__(256) void prep_b_kernel(
    const float* __restrict__ src, float* __restrict__ dst, int N, int K)
{
    __shared__ float tile[32 * 132];
    const int tid = threadIdx.x;
    const int nkc = K >> 5;
    const int nb = blockIdx.x / nkc;
    const int kc = blockIdx.x % nkc;
    const float* s0 = src + (size_t)(kc * 32) * N + nb * 128;

#pragma unroll
    for (int p = 0; p < 4; p++) {
        int id = tid + p * 256;
        int k = id >> 5, n4 = (id & 31) << 2;
        float4 v = *reinterpret_cast<const float4*>(s0 + (size_t)k * N + n4);
        *reinterpret_cast<float4*>(&tile[k * 132 + n4]) = v;
    }
    __syncthreads();

    float* d0 = dst + (size_t)blockIdx.x * 4096;
#pragma unroll
    for (int p = 0; p < 4; p++) {
        int q = tid + p * 256;
        int fb = q >> 4;
        int ks = fb >> 4, n8 = fb & 15;
        int o4 = (q & 15) << 2;
        uint4 o;
        uint32_t* ov = reinterpret_cast<uint32_t*>(&o);
#pragma unroll
        for (int i = 0; i < 4; i++) {
            int off = o4 + i;
            int g = off >> 3, c = (off & 7) >> 1, u = off & 1;
            ov[i] = f2tf(tile[(ks * 8 + u * 4 + c) * 132 + n8 * 8 + g]);
        }
        *reinterpret_cast<uint4*>(d0 + q * 4) = o;
    }
}

// ===========================================================================
// TF32 mma.sync GEMM — R12 consume path, 3-stage cp.async pipeline
// (wait_group 1: each stage gets a full extra iteration of latency cover).
// round_out=1: epilogue stores tf32-rounded values (qkv -> attention).
// ===========================================================================
#define AFRAG_FLOATS 4224                 // 32 frags * 132  (528 B, 16-aligned)
#define BFRAG_FLOATS 4352                 // 64 frags * 68   (272 B, 16-aligned)
#define STAGE_FLOATS (AFRAG_FLOATS + BFRAG_FLOATS)
#define GEMM_SMEM_BYTES (3 * STAGE_FLOATS * 4)   // 102912

__global__ __launch_bounds__(256) void gemm_fm_kernel(
    const float* __restrict__ Afm, const float* __restrict__ Bfm,
    const float* __restrict__ bias, float* __restrict__ C,
    int M, int N, int K, int round_out)
{
    extern __shared__ float sh[];
    uint32_t smb;
    asm("{ .reg .u64 t; cvta.to.shared.u64 t, %1; cvt.u32.u64 %0, t; }"
        : "=r"(smb) : "l"(sh));

    const int tid  = threadIdx.x;
    const int lane = tid & 31;
    const int wid  = tid >> 5;
    const int wm   = wid & 1;
    const int wn   = wid >> 1;
    const int g    = lane >> 2;
    const int c    = lane & 3;

    const int nkc = K >> 5;
    const int mb  = blockIdx.y;
    const int nb  = blockIdx.x;
    const float* Ab = Afm + (size_t)mb * nkc * 4096;
    const float* Bb = Bfm + (size_t)nb * nkc * 4096;

    float acc[4][4][4];
#pragma unroll
    for (int i = 0; i < 4; i++)
#pragma unroll
        for (int j = 0; j < 4; j++)
#pragma unroll
            for (int l = 0; l < 4; l++) acc[i][j][l] = 0.f;

    auto stage_cp = [&](int s, int kc) {
        const float* ag = Ab + (size_t)kc * 4096;
        const float* bg = Bb + (size_t)kc * 4096;
        uint32_t sa = smb + (uint32_t)(s * STAGE_FLOATS) * 4;
        uint32_t sb = sa + AFRAG_FLOATS * 4;
#pragma unroll
        for (int p = 0; p < 4; p++) {
            int ch = tid + p * 256;
            int f = ch >> 5, off = ch & 31;
            cp16(sa + (uint32_t)(f * 528 + off * 16), ag + ch * 4);
        }
#pragma unroll
        for (int p = 0; p < 4; p++) {
            int ch = tid + p * 256;
            int fb = ch >> 4, off = ch & 15;
            cp16(sb + (uint32_t)(fb * 272 + off * 16), bg + ch * 4);
        }
    };

    auto compute = [&](int s, int ks) {
        const float* as_ = sh + s * STAGE_FLOATS;
        const float* bs_ = as_ + AFRAG_FLOATS;
        uint32_t af[4][4], bfr[4][2];
#pragma unroll
        for (int mf = 0; mf < 4; mf++) {
            float4 v = *reinterpret_cast<const float4*>(
                as_ + ((wm * 4 + mf) * 4 + ks) * 132 + lane * 4);
            af[mf][0] = __float_as_uint(v.x);
            af[mf][1] = __float_as_uint(v.y);
            af[mf][2] = __float_as_uint(v.z);
            af[mf][3] = __float_as_uint(v.w);
        }
#pragma unroll
        for (int nf = 0; nf < 4; nf++) {
            float2 v = *reinterpret_cast<const float2*>(
                bs_ + (ks * 16 + wn * 4 + nf) * 68 + lane * 2);
            bfr[nf][0] = __float_as_uint(v.x);
            bfr[nf][1] = __float_as_uint(v.y);
        }
#pragma unroll
        for (int mf = 0; mf < 4; mf++)
#pragma unroll
            for (int nf = 0; nf < 4; nf++)
                mma_tf32(acc[mf][nf], af[mf], bfr[nf]);
    };

    const int niter = nkc;

    // prologue: stages 0 and 1 in flight
    stage_cp(0, 0);
    asm volatile("cp.async.commit_group;");
    stage_cp(1, 1);
    asm volatile("cp.async.commit_group;");

    int s = 0;
    for (int it = 0; it < niter; it++) {
        asm volatile("cp.async.wait_group 1;");   // oldest (stage s) resident
        __syncthreads();
        if (it + 2 < niter) stage_cp((s + 2 >= 3) ? s - 1 : s + 2, it + 2);
        asm volatile("cp.async.commit_group;");   // keep group count uniform
        compute(s, 0);
        compute(s, 1);
        compute(s, 2);
        compute(s, 3);
        s = (s + 1 == 3) ? 0 : s + 1;
    }

    // epilogue: acc + bias -> C (optionally tf32-rounded)
    const int m0 = mb * 128;
    const int n0 = nb * 128;
#pragma unroll
    for (int mf = 0; mf < 4; mf++) {
        int r = m0 + wm * 64 + mf * 16 + g;
#pragma unroll
        for (int nf = 0; nf < 4; nf++) {
            int col = n0 + wn * 32 + nf * 8 + c * 2;
            float b0v = bias[col], b1v = bias[col + 1];
            float v00 = acc[mf][nf][0] + b0v, v01 = acc[mf][nf][1] + b1v;
            float v10 = acc[mf][nf][2] + b0v, v11 = acc[mf][nf][3] + b1v;
            if (round_out) {
                v00 = __uint_as_float(f2tf(v00));
                v01 = __uint_as_float(f2tf(v01));
                v10 = __uint_as_float(f2tf(v10));
                v11 = __uint_as_float(f2tf(v11));
            }
            *reinterpret_cast<float2*>(&C[(size_t)r * N + col])       = make_float2(v00, v01);
            *reinterpret_cast<float2*>(&C[(size_t)(r + 8) * N + col]) = make_float2(v10, v11);
        }
    }
}

// ===========================================================================
// Tensor-core flash attention. qkv pre-rounded tf32 (plain K/V loads).
// K(kb+1) prefetch hoisted BEFORE the QK phase for a full extra phase of
// latency cover. fexp for softmax.
// ===========================================================================
#define AT_BM 128
#define AT_BN 64
#define KSTR 132
#define VSTR 136
#define PSTR 68
#define SM_QF 0
#define SM_K0 16384
#define SM_K1 (16384 + 8448)
#define SM_V  (16384 + 16896)
#define SM_P  (16384 + 16896 + 8704)
#define AT_SMEM_FLOATS (16384 + 16896 + 8704 + 8704)
#define AT_SMEM_BYTES  (AT_SMEM_FLOATS * 4)

__global__ __launch_bounds__(256) void flash_attn_tc_kernel(
    const float* __restrict__ qkv, float* __restrict__ att)
{
    extern __shared__ float sm[];
    const int tid  = threadIdx.x;
    const int lane = tid & 31;
    const int w    = tid >> 5;
    const int g    = lane >> 2;
    const int c    = lane & 3;
    const int qb   = (int)gridDim.x - 1 - (int)blockIdx.x;
    const int h    = blockIdx.y;
    const int b    = blockIdx.z;
    const int q0   = qb * AT_BM;
    const size_t base = (size_t)b * SS_ * N_QKV + (size_t)h * HD;
    const float scale = 0.08838834764831845f;

    uint32_t smb;
    asm("{ .reg .u64 t; cvta.to.shared.u64 t, %1; cvt.u32.u64 %0, t; }" : "=r"(smb) : "l"(sm));

#pragma unroll
    for (int i = 0; i < 16; i++) {
        int id = tid + i * 256;
        int r  = id >> 5;
        int c4 = (id & 31) << 2;
        float4 v = *reinterpret_cast<const float4*>(&qkv[base + (size_t)(q0 + r) * N_QKV + c4]);
        int rb = r >> 4, rr = r & 15, gg = rr & 7, half = rr >> 3;
        int ks = c4 >> 3, khalf = (c4 >> 2) & 1;
        int reg = half + 2 * khalf;
        int ba = ((rb * 16 + ks) * 32) * 4 + reg;
        float vv[4] = {v.x, v.y, v.z, v.w};
#pragma unroll
        for (int j = 0; j < 4; j++)
            sm[SM_QF + ba + (gg * 4 + j) * 4] = __uint_as_float(f2tf(vv[j] * scale));
    }

    float o[16][4];
#pragma unroll
    for (int nt = 0; nt < 16; nt++)
#pragma unroll
        for (int l = 0; l < 4; l++) o[nt][l] = 0.f;
    float m0 = -INFINITY, m1 = -INFINITY, l0 = 0.f, l1 = 0.f;

    const int r0 = q0 + w * 16 + g;
    const int nkb = 2 * qb + 2;
    const uint32_t pbase = SM_P + w * (16 * PSTR);

#pragma unroll
    for (int i = 0; i < 8; i++) {
        int id = tid + i * 256;
        int row = id >> 5, c16 = (id & 31) << 2;
        cp16(smb + (uint32_t)(SM_K0 + row * KSTR + c16) * 4,
             &qkv[base + (size_t)row * N_QKV + DD + c16]);
    }
    asm volatile("cp.async.commit_group;");

    for (int kb = 0; kb < nkb; kb++) {
        const int k0 = kb * AT_BN;
        const int sK = (kb & 1) ? SM_K1 : SM_K0;

        // issue V(kb)
#pragma unroll
        for (int i = 0; i < 8; i++) {
            int id = tid + i * 256;
            int row = id >> 5, c16 = (id & 31) << 2;
            cp16(smb + (uint32_t)(SM_V + row * VSTR + c16) * 4,
                 &qkv[base + (size_t)(k0 + row) * N_QKV + 2 * DD + c16]);
        }
        asm volatile("cp.async.commit_group;");
        asm volatile("cp.async.wait_group 1;");   // K(kb) resident
        __syncthreads();

        // issue K(kb+1) now — full QK phase of latency cover
        if (kb + 1 < nkb) {
            const int sKn = (kb & 1) ? SM_K0 : SM_K1;
            const int k0n = (kb + 1) * AT_BN;
#pragma unroll
            for (int i = 0; i < 8; i++) {
                int id = tid + i * 256;
                int row = id >> 5, c16 = (id & 31) << 2;
                cp16(smb + (uint32_t)(sKn + row * KSTR + c16) * 4,
                     &qkv[base + (size_t)(k0n + row) * N_QKV + DD + c16]);
            }
        }
        asm volatile("cp.async.commit_group;");

        // ---- QK ----
        float s[8][4];
#pragma unroll
        for (int nt = 0; nt < 8; nt++)
#pragma unroll
            for (int l = 0; l < 4; l++) s[nt][l] = 0.f;

#pragma unroll
        for (int ks = 0; ks < 16; ks++) {
            float4 qa = *reinterpret_cast<const float4*>(&sm[SM_QF + ((w * 16 + ks) * 32 + lane) * 4]);
            uint32_t a[4] = {__float_as_uint(qa.x), __float_as_uint(qa.y),
                             __float_as_uint(qa.z), __float_as_uint(qa.w)};
#pragma unroll
            for (int nt = 0; nt < 8; nt++) {
                const float* kp = &sm[sK + (nt * 8 + g) * KSTR + ks * 8 + c];
                uint32_t bfr[2] = {__float_as_uint(kp[0]), __float_as_uint(kp[4])};
                mma_tf32(s[nt], a, bfr);
            }
        }

        if (k0 + 63 > q0 + w * 16) {
#pragma unroll
            for (int nt = 0; nt < 8; nt++) {
                int col = k0 + nt * 8 + 2 * c;
                if (col     > r0)     s[nt][0] = -INFINITY;
                if (col + 1 > r0)     s[nt][1] = -INFINITY;
                if (col     > r0 + 8) s[nt][2] = -INFINITY;
                if (col + 1 > r0 + 8) s[nt][3] = -INFINITY;
            }
        }

        float mt0 = -INFINITY, mt1 = -INFINITY;
#pragma unroll
        for (int nt = 0; nt < 8; nt++) {
            mt0 = fmaxf(mt0, fmaxf(s[nt][0], s[nt][1]));
            mt1 = fmaxf(mt1, fmaxf(s[nt][2], s[nt][3]));
        }
        mt0 = fmaxf(mt0, __shfl_xor_sync(0xffffffffu, mt0, 1));
        mt0 = fmaxf(mt0, __shfl_xor_sync(0xffffffffu, mt0, 2));
        mt1 = fmaxf(mt1, __shfl_xor_sync(0xffffffffu, mt1, 1));
        mt1 = fmaxf(mt1, __shfl_xor_sync(0xffffffffu, mt1, 2));

        float mn0 = fmaxf(m0, mt0), mn1 = fmaxf(m1, mt1);
        float cr0 = fexp(m0 - mn0), cr1 = fexp(m1 - mn1);
        m0 = mn0; m1 = mn1;

        float ps0 = 0.f, ps1 = 0.f;
#pragma unroll
        for (int nt = 0; nt < 8; nt++) {
            float p00 = fexp(s[nt][0] - m0);
            float p01 = fexp(s[nt][1] - m0);
            float p10 = fexp(s[nt][2] - m1);
            float p11 = fexp(s[nt][3] - m1);
            ps0 += p00 + p01;
            ps1 += p10 + p11;
            uint2 u0 = make_uint2(f2tf(p00), f2tf(p01));
            uint2 u1 = make_uint2(f2tf(p10), f2tf(p11));
            *reinterpret_cast<uint2*>(&sm[pbase + g * PSTR + nt * 8 + 2 * c])       = u0;
            *reinterpret_cast<uint2*>(&sm[pbase + (g + 8) * PSTR + nt * 8 + 2 * c]) = u1;
        }
        ps0 += __shfl_xor_sync(0xffffffffu, ps0, 1);
        ps0 += __shfl_xor_sync(0xffffffffu, ps0, 2);
        ps1 += __shfl_xor_sync(0xffffffffu, ps1, 1);
        ps1 += __shfl_xor_sync(0xffffffffu, ps1, 2);
        l0 = l0 * cr0 + ps0;
        l1 = l1 * cr1 + ps1;

#pragma unroll
        for (int nt = 0; nt < 16; nt++) {
            o[nt][0] *= cr0; o[nt][1] *= cr0;
            o[nt][2] *= cr1; o[nt][3] *= cr1;
        }

        asm volatile("cp.async.wait_group 1;");   // V(kb) resident
        __syncthreads();

#pragma unroll
        for (int ks2 = 0; ks2 < 8; ks2++) {
            uint32_t a[4];
            a[0] = __float_as_uint(sm[pbase + g * PSTR + ks2 * 8 + c]);
            a[1] = __float_as_uint(sm[pbase + (g + 8) * PSTR + ks2 * 8 + c]);
            a[2] = __float_as_uint(sm[pbase + g * PSTR + ks2 * 8 + c + 4]);
            a[3] = __float_as_uint(sm[pbase + (g + 8) * PSTR + ks2 * 8 + c + 4]);
#pragma unroll
            for (int nt = 0; nt < 16; nt++) {
                uint32_t bfr[2] = {
                    __float_as_uint(sm[SM_V + (ks2 * 8 + c) * VSTR + nt * 8 + g]),
                    __float_as_uint(sm[SM_V + (ks2 * 8 + c + 4) * VSTR + nt * 8 + g])};
                mma_tf32(o[nt], a, bfr);
            }
        }
        __syncthreads();
    }

    float il0 = 1.f / l0, il1 = 1.f / l1;
    size_t ob = ((size_t)(b * SS_) + q0 + w * 16) * DD + (size_t)h * HD;
#pragma unroll
    for (int nt = 0; nt < 16; nt++) {
        int col = nt * 8 + 2 * c;
        uint2 w0 = make_uint2(f2tf(o[nt][0] * il0), f2tf(o[nt][1] * il0));
        uint2 w1 = make_uint2(f2tf(o[nt][2] * il1), f2tf(o[nt][3] * il1));
        *reinterpret_cast<uint2*>(&att[ob + (size_t)g * DD + col])       = w0;
        *reinterpret_cast<uint2*>(&att[ob + (size_t)(g + 8) * DD + col]) = w1;
    }
}

// ===========================================================================
// Launch
// ===========================================================================
extern "C" void kernel_launch(void* const* d_in, const int* in_sizes, int n_in,
                              void* d_out, int out_size)
{
    const float* x      = (const float*)d_in[0];
    const float* W_qkv  = (const float*)d_in[1];
    const float* b_qkv  = (const float*)d_in[2];
    const float* W_out  = (const float*)d_in[3];
    const float* b_out  = (const float*)d_in[4];
    float* out          = (float*)d_out;

    float *qkv_p, *att_p, *xfm_p, *attfm_p, *w1fm_p, *w2fm_p;
    cudaGetSymbolAddress((void**)&qkv_p,   g_qkv);
    cudaGetSymbolAddress((void**)&att_p,   g_att);
    cudaGetSymbolAddress((void**)&xfm_p,   g_xfm);
    cudaGetSymbolAddress((void**)&attfm_p, g_attfm);
    cudaGetSymbolAddress((void**)&w1fm_p,  g_w1fm);
    cudaGetSymbolAddress((void**)&w2fm_p,  g_w2fm);

    cudaFuncSetAttribute(gemm_fm_kernel,
                         cudaFuncAttributeMaxDynamicSharedMemorySize, GEMM_SMEM_BYTES);
    cudaFuncSetAttribute(flash_attn_tc_kernel,
                         cudaFuncAttributeMaxDynamicSharedMemorySize, AT_SMEM_BYTES);

    // One-time operand formatting (rounds to tf32 + fragment-major layout)
    prep_a_kernel<<<(M_TOT / 128) * (DD / 32), 256>>>(x, xfm_p, DD);
    prep_b_kernel<<<(N_QKV / 128) * (DD / 32), 256>>>(W_qkv, w1fm_p, N_QKV, DD);
    prep_b_kernel<<<(DD / 128) * (DD / 32), 256>>>(W_out, w2fm_p, DD, DD);

    // QKV projection (tf32-rounded output so attention skips cvt on K/V)
    gemm_fm_kernel<<<dim3(N_QKV / 128, M_TOT / 128), 256, GEMM_SMEM_BYTES>>>(
        xfm_p, w1fm_p, b_qkv, qkv_p, M_TOT, N_QKV, DD, 1);

    // Fused causal attention (tensor-core)
    flash_attn_tc_kernel<<<dim3(SS_ / AT_BM, HH, BB), 256, AT_SMEM_BYTES>>>(qkv_p, att_p);

    // Format attention output as A for the out-projection
    prep_a_kernel<<<(M_TOT / 128) * (DD / 32), 256>>>(att_p, attfm_p, DD);

    // Output projection (raw fp32 output — final answer)
    gemm_fm_kernel<<<dim3(DD / 128, M_TOT / 128), 256, GEMM_SMEM_BYTES>>>(
        attfm_p, w2fm_p, b_out, out, M_TOT, DD, DD, 0);
}

// round 17
// speedup vs baseline: 1.0805x; 1.0121x over previous
#include <cuda_runtime.h>
#include <math.h>
#include <stdint.h>

#define BB 2
#define SS_ 2048
#define DD 2048
#define HH 16
#define HD 128
#define M_TOT (BB * SS_)     // 4096
#define N_QKV (3 * DD)       // 6144

__device__ float g_qkv[M_TOT * N_QKV];     // qkv rows (tf32-rounded by gemm epilogue)
__device__ float g_xfm [M_TOT * DD];       // x, fragment-major A
__device__ float g_attfm[M_TOT * DD];      // attention out, fragment-major A (direct)
__device__ float g_w1fm[DD * N_QKV];       // W_qkv, fragment-major B
__device__ float g_w2fm[DD * DD];          // W_out, fragment-major B

__device__ __forceinline__ uint32_t f2tf(float f) {
    uint32_t u;
    asm("cvt.rna.tf32.f32 %0, %1;" : "=r"(u) : "f"(f));
    return u;
}

// FMA-pipe exp: exp(x) = 2^(x*log2e), magic-number split, degree-5 poly.
__device__ __forceinline__ float fexp(float x) {
    x = fmaxf(x, -87.0f);
    const float L2E = 1.4426950408889634f;
    float y  = fmaf(x, L2E, 12582912.0f);
    int   ni = __float_as_int(y);
    float nf = y - 12582912.0f;
    float f  = fmaf(x, L2E, -nf);
    float p  = 0.00133335581f;
    p = fmaf(p, f, 0.00961812911f);
    p = fmaf(p, f, 0.0555041087f);
    p = fmaf(p, f, 0.240226507f);
    p = fmaf(p, f, 0.693147180f);
    p = fmaf(p, f, 1.0f);
    float scale = __int_as_float((ni - 0x4B400000 + 127) << 23);
    return scale * p;
}

__device__ __forceinline__ void mma_tf32(float* d, const uint32_t* a, const uint32_t* b) {
    asm volatile(
        "mma.sync.aligned.m16n8k8.row.col.f32.tf32.tf32.f32 "
        "{%0,%1,%2,%3}, {%4,%5,%6,%7}, {%8,%9}, {%0,%1,%2,%3};\n"
        : "+f"(d[0]), "+f"(d[1]), "+f"(d[2]), "+f"(d[3])
        : "r"(a[0]), "r"(a[1]), "r"(a[2]), "r"(a[3]), "r"(b[0]), "r"(b[1]));
}

__device__ __forceinline__ void cp16(uint32_t saddr, const float* gptr) {
    asm volatile("cp.async.cg.shared.global [%0], [%1], 16;" :: "r"(saddr), "l"(gptr));
}

// ===========================================================================
// Prep A: row-major [M,K] fp32 -> fragment-major tf32 blocks (as R12).
// (used only for x now; attention writes its A-fragments directly)
// ===========================================================================
__global__ __launch_bounds__(256) void prep_a_kernel(
    const float* __restrict__ src, float* __restrict__ dst, int K)
{
    __shared__ float tile[128 * 36];
    const int tid = threadIdx.x;
    const int nkc = K >> 5;
    const int mb = blockIdx.x / nkc;
    const int kc = blockIdx.x % nkc;
    const float* s0 = src + (size_t)mb * 128 * K + kc * 32;

#pragma unroll
    for (int p = 0; p < 4; p++) {
        int id = tid + p * 256;
        int row = id >> 3, c4 = (id & 7) << 2;
        float4 v = *reinterpret_cast<const float4*>(s0 + (size_t)row * K + c4);
        float* t = &tile[row * 36 + c4];
        t[0] = v.x; t[1] = v.y; t[2] = v.z; t[3] = v.w;
    }
    __syncthreads();

    float* d0 = dst + (size_t)blockIdx.x * 4096;
#pragma unroll
    for (int p = 0; p < 4; p++) {
        int q = tid + p * 256;
        int f = q >> 5;
        int l = q & 31;
        int g = l >> 2, c = l & 3;
        int mf = f >> 2, ks = f & 3;
        const float* tl = &tile[(mf * 16 + g) * 36 + ks * 8 + c];
        uint4 o;
        o.x = f2tf(tl[0]);
        o.y = f2tf(tl[8 * 36]);
        o.z = f2tf(tl[4]);
        o.w = f2tf(tl[8 * 36 + 4]);
        *reinterpret_cast<uint4*>(d0 + q * 4) = o;
    }
}

// ===========================================================================
// Prep B: row-major W[K,N] fp32 -> fragment-major tf32 blocks (as R12).
// ===========================================================================
__global__ __launch_bounds__(256) void prep_b_kernel(
    const float* __restrict__ src, float* __restrict__ dst, int N, int K)
{
    __shared__ float tile[32 * 132];
    const int tid = threadIdx.x;
    const int nkc = K >> 5;
    const int nb = blockIdx.x / nkc;
    const int kc = blockIdx.x % nkc;
    const float* s0 = src + (size_t)(kc * 32) * N + nb * 128;

#pragma unroll
    for (int p = 0; p < 4; p++) {
        int id = tid + p * 256;
        int k = id >> 5, n4 = (id & 31) << 2;
        float4 v = *reinterpret_cast<const float4*>(s0 + (size_t)k * N + n4);
        *reinterpret_cast<float4*>(&tile[k * 132 + n4]) = v;
    }
    __syncthreads();

    float* d0 = dst + (size_t)blockIdx.x * 4096;
#pragma unroll
    for (int p = 0; p < 4; p++) {
        int q = tid + p * 256;
        int fb = q >> 4;
        int ks = fb >> 4, n8 = fb & 15;
        int o4 = (q & 15) << 2;
        uint4 o;
        uint32_t* ov = reinterpret_cast<uint32_t*>(&o);
#pragma unroll
        for (int i = 0; i < 4; i++) {
            int off = o4 + i;
            int g = off >> 3, c = (off & 7) >> 1, u = off & 1;
            ov[i] = f2tf(tile[(ks * 8 + u * 4 + c) * 132 + n8 * 8 + g]);
        }
        *reinterpret_cast<uint4*>(d0 + q * 4) = o;
    }
}

// ===========================================================================
// TF32 mma.sync GEMM — R15 (3-stage cp.async pipeline, wait_group 1).
// round_out=1: epilogue stores tf32-rounded values (qkv -> attention).
// ===========================================================================
#define AFRAG_FLOATS 4224                 // 32 frags * 132  (528 B, 16-aligned)
#define BFRAG_FLOATS 4352                 // 64 frags * 68   (272 B, 16-aligned)
#define STAGE_FLOATS (AFRAG_FLOATS + BFRAG_FLOATS)
#define GEMM_SMEM_BYTES (3 * STAGE_FLOATS * 4)   // 102912

__global__ __launch_bounds__(256) void gemm_fm_kernel(
    const float* __restrict__ Afm, const float* __restrict__ Bfm,
    const float* __restrict__ bias, float* __restrict__ C,
    int M, int N, int K, int round_out)
{
    extern __shared__ float sh[];
    uint32_t smb;
    asm("{ .reg .u64 t; cvta.to.shared.u64 t, %1; cvt.u32.u64 %0, t; }"
        : "=r"(smb) : "l"(sh));

    const int tid  = threadIdx.x;
    const int lane = tid & 31;
    const int wid  = tid >> 5;
    const int wm   = wid & 1;
    const int wn   = wid >> 1;
    const int g    = lane >> 2;
    const int c    = lane & 3;

    const int nkc = K >> 5;
    const int mb  = blockIdx.y;
    const int nb  = blockIdx.x;
    const float* Ab = Afm + (size_t)mb * nkc * 4096;
    const float* Bb = Bfm + (size_t)nb * nkc * 4096;

    float acc[4][4][4];
#pragma unroll
    for (int i = 0; i < 4; i++)
#pragma unroll
        for (int j = 0; j < 4; j++)
#pragma unroll
            for (int l = 0; l < 4; l++) acc[i][j][l] = 0.f;

    auto stage_cp = [&](int s, int kc) {
        const float* ag = Ab + (size_t)kc * 4096;
        const float* bg = Bb + (size_t)kc * 4096;
        uint32_t sa = smb + (uint32_t)(s * STAGE_FLOATS) * 4;
        uint32_t sb = sa + AFRAG_FLOATS * 4;
#pragma unroll
        for (int p = 0; p < 4; p++) {
            int ch = tid + p * 256;
            int f = ch >> 5, off = ch & 31;
            cp16(sa + (uint32_t)(f * 528 + off * 16), ag + ch * 4);
        }
#pragma unroll
        for (int p = 0; p < 4; p++) {
            int ch = tid + p * 256;
            int fb = ch >> 4, off = ch & 15;
            cp16(sb + (uint32_t)(fb * 272 + off * 16), bg + ch * 4);
        }
    };

    auto compute = [&](int s, int ks) {
        const float* as_ = sh + s * STAGE_FLOATS;
        const float* bs_ = as_ + AFRAG_FLOATS;
        uint32_t af[4][4], bfr[4][2];
#pragma unroll
        for (int mf = 0; mf < 4; mf++) {
            float4 v = *reinterpret_cast<const float4*>(
                as_ + ((wm * 4 + mf) * 4 + ks) * 132 + lane * 4);
            af[mf][0] = __float_as_uint(v.x);
            af[mf][1] = __float_as_uint(v.y);
            af[mf][2] = __float_as_uint(v.z);
            af[mf][3] = __float_as_uint(v.w);
        }
#pragma unroll
        for (int nf = 0; nf < 4; nf++) {
            float2 v = *reinterpret_cast<const float2*>(
                bs_ + (ks * 16 + wn * 4 + nf) * 68 + lane * 2);
            bfr[nf][0] = __float_as_uint(v.x);
            bfr[nf][1] = __float_as_uint(v.y);
        }
#pragma unroll
        for (int mf = 0; mf < 4; mf++)
#pragma unroll
            for (int nf = 0; nf < 4; nf++)
                mma_tf32(acc[mf][nf], af[mf], bfr[nf]);
    };

    const int niter = nkc;

    stage_cp(0, 0);
    asm volatile("cp.async.commit_group;");
    stage_cp(1, 1);
    asm volatile("cp.async.commit_group;");

    int s = 0;
    for (int it = 0; it < niter; it++) {
        asm volatile("cp.async.wait_group 1;");
        __syncthreads();
        if (it + 2 < niter) stage_cp((s + 2 >= 3) ? s - 1 : s + 2, it + 2);
        asm volatile("cp.async.commit_group;");
        compute(s, 0);
        compute(s, 1);
        compute(s, 2);
        compute(s, 3);
        s = (s + 1 == 3) ? 0 : s + 1;
    }

    const int m0 = mb * 128;
    const int n0 = nb * 128;
#pragma unroll
    for (int mf = 0; mf < 4; mf++) {
        int r = m0 + wm * 64 + mf * 16 + g;
#pragma unroll
        for (int nf = 0; nf < 4; nf++) {
            int col = n0 + wn * 32 + nf * 8 + c * 2;
            float b0v = bias[col], b1v = bias[col + 1];
            float v00 = acc[mf][nf][0] + b0v, v01 = acc[mf][nf][1] + b1v;
            float v10 = acc[mf][nf][2] + b0v, v11 = acc[mf][nf][3] + b1v;
            if (round_out) {
                v00 = __uint_as_float(f2tf(v00));
                v01 = __uint_as_float(f2tf(v01));
                v10 = __uint_as_float(f2tf(v10));
                v11 = __uint_as_float(f2tf(v11));
            }
            *reinterpret_cast<float2*>(&C[(size_t)r * N + col])       = make_float2(v00, v01);
            *reinterpret_cast<float2*>(&C[(size_t)(r + 8) * N + col]) = make_float2(v10, v11);
        }
    }
}

// ===========================================================================
// Tensor-core flash attention (R15 mainloop). Epilogue now writes the
// out-projection's A-operand DIRECTLY in fragment-major tf32 layout via a
// per-warp smem transpose (reuses V+P region after final barrier).
// ===========================================================================
#define AT_BM 128
#define AT_BN 64
#define KSTR 132
#define VSTR 136
#define PSTR 68
#define SM_QF 0
#define SM_K0 16384
#define SM_K1 (16384 + 8448)
#define SM_V  (16384 + 16896)
#define SM_P  (16384 + 16896 + 8704)
#define AT_SMEM_FLOATS (16384 + 16896 + 8704 + 8704)
#define AT_SMEM_BYTES  (AT_SMEM_FLOATS * 4)

__global__ __launch_bounds__(256) void flash_attn_tc_kernel(
    const float* __restrict__ qkv, float* __restrict__ attfm)
{
    extern __shared__ float sm[];
    const int tid  = threadIdx.x;
    const int lane = tid & 31;
    const int w    = tid >> 5;
    const int g    = lane >> 2;
    const int c    = lane & 3;
    const int qb   = (int)gridDim.x - 1 - (int)blockIdx.x;
    const int h    = blockIdx.y;
    const int b    = blockIdx.z;
    const int q0   = qb * AT_BM;
    const size_t base = (size_t)b * SS_ * N_QKV + (size_t)h * HD;
    const float scale = 0.08838834764831845f;

    uint32_t smb;
    asm("{ .reg .u64 t; cvta.to.shared.u64 t, %1; cvt.u32.u64 %0, t; }" : "=r"(smb) : "l"(sm));

#pragma unroll
    for (int i = 0; i < 16; i++) {
        int id = tid + i * 256;
        int r  = id >> 5;
        int c4 = (id & 31) << 2;
        float4 v = *reinterpret_cast<const float4*>(&qkv[base + (size_t)(q0 + r) * N_QKV + c4]);
        int rb = r >> 4, rr = r & 15, gg = rr & 7, half = rr >> 3;
        int ks = c4 >> 3, khalf = (c4 >> 2) & 1;
        int reg = half + 2 * khalf;
        int ba = ((rb * 16 + ks) * 32) * 4 + reg;
        float vv[4] = {v.x, v.y, v.z, v.w};
#pragma unroll
        for (int j = 0; j < 4; j++)
            sm[SM_QF + ba + (gg * 4 + j) * 4] = __uint_as_float(f2tf(vv[j] * scale));
    }

    float o[16][4];
#pragma unroll
    for (int nt = 0; nt < 16; nt++)
#pragma unroll
        for (int l = 0; l < 4; l++) o[nt][l] = 0.f;
    float m0 = -INFINITY, m1 = -INFINITY, l0 = 0.f, l1 = 0.f;

    const int r0 = q0 + w * 16 + g;
    const int nkb = 2 * qb + 2;
    const uint32_t pbase = SM_P + w * (16 * PSTR);

#pragma unroll
    for (int i = 0; i < 8; i++) {
        int id = tid + i * 256;
        int row = id >> 5, c16 = (id & 31) << 2;
        cp16(smb + (uint32_t)(SM_K0 + row * KSTR + c16) * 4,
             &qkv[base + (size_t)row * N_QKV + DD + c16]);
    }
    asm volatile("cp.async.commit_group;");

    for (int kb = 0; kb < nkb; kb++) {
        const int k0 = kb * AT_BN;
        const int sK = (kb & 1) ? SM_K1 : SM_K0;

        // issue V(kb)
#pragma unroll
        for (int i = 0; i < 8; i++) {
            int id = tid + i * 256;
            int row = id >> 5, c16 = (id & 31) << 2;
            cp16(smb + (uint32_t)(SM_V + row * VSTR + c16) * 4,
                 &qkv[base + (size_t)(k0 + row) * N_QKV + 2 * DD + c16]);
        }
        asm volatile("cp.async.commit_group;");
        asm volatile("cp.async.wait_group 1;");   // K(kb) resident
        __syncthreads();

        // issue K(kb+1) early (full QK phase of latency cover)
        if (kb + 1 < nkb) {
            const int sKn = (kb & 1) ? SM_K0 : SM_K1;
            const int k0n = (kb + 1) * AT_BN;
#pragma unroll
            for (int i = 0; i < 8; i++) {
                int id = tid + i * 256;
                int row = id >> 5, c16 = (id & 31) << 2;
                cp16(smb + (uint32_t)(sKn + row * KSTR + c16) * 4,
                     &qkv[base + (size_t)(k0n + row) * N_QKV + DD + c16]);
            }
        }
        asm volatile("cp.async.commit_group;");

        // ---- QK ----
        float s[8][4];
#pragma unroll
        for (int nt = 0; nt < 8; nt++)
#pragma unroll
            for (int l = 0; l < 4; l++) s[nt][l] = 0.f;

#pragma unroll
        for (int ks = 0; ks < 16; ks++) {
            float4 qa = *reinterpret_cast<const float4*>(&sm[SM_QF + ((w * 16 + ks) * 32 + lane) * 4]);
            uint32_t a[4] = {__float_as_uint(qa.x), __float_as_uint(qa.y),
                             __float_as_uint(qa.z), __float_as_uint(qa.w)};
#pragma unroll
            for (int nt = 0; nt < 8; nt++) {
                const float* kp = &sm[sK + (nt * 8 + g) * KSTR + ks * 8 + c];
                uint32_t bfr[2] = {__float_as_uint(kp[0]), __float_as_uint(kp[4])};
                mma_tf32(s[nt], a, bfr);
            }
        }

        if (k0 + 63 > q0 + w * 16) {
#pragma unroll
            for (int nt = 0; nt < 8; nt++) {
                int col = k0 + nt * 8 + 2 * c;
                if (col     > r0)     s[nt][0] = -INFINITY;
                if (col + 1 > r0)     s[nt][1] = -INFINITY;
                if (col     > r0 + 8) s[nt][2] = -INFINITY;
                if (col + 1 > r0 + 8) s[nt][3] = -INFINITY;
            }
        }

        float mt0 = -INFINITY, mt1 = -INFINITY;
#pragma unroll
        for (int nt = 0; nt < 8; nt++) {
            mt0 = fmaxf(mt0, fmaxf(s[nt][0], s[nt][1]));
            mt1 = fmaxf(mt1, fmaxf(s[nt][2], s[nt][3]));
        }
        mt0 = fmaxf(mt0, __shfl_xor_sync(0xffffffffu, mt0, 1));
        mt0 = fmaxf(mt0, __shfl_xor_sync(0xffffffffu, mt0, 2));
        mt1 = fmaxf(mt1, __shfl_xor_sync(0xffffffffu, mt1, 1));
        mt1 = fmaxf(mt1, __shfl_xor_sync(0xffffffffu, mt1, 2));

        float mn0 = fmaxf(m0, mt0), mn1 = fmaxf(m1, mt1);
        float cr0 = fexp(m0 - mn0), cr1 = fexp(m1 - mn1);
        m0 = mn0; m1 = mn1;

        float ps0 = 0.f, ps1 = 0.f;
#pragma unroll
        for (int nt = 0; nt < 8; nt++) {
            float p00 = fexp(s[nt][0] - m0);
            float p01 = fexp(s[nt][1] - m0);
            float p10 = fexp(s[nt][2] - m1);
            float p11 = fexp(s[nt][3] - m1);
            ps0 += p00 + p01;
            ps1 += p10 + p11;
            uint2 u0 = make_uint2(f2tf(p00), f2tf(p01));
            uint2 u1 = make_uint2(f2tf(p10), f2tf(p11));
            *reinterpret_cast<uint2*>(&sm[pbase + g * PSTR + nt * 8 + 2 * c])       = u0;
            *reinterpret_cast<uint2*>(&sm[pbase + (g + 8) * PSTR + nt * 8 + 2 * c]) = u1;
        }
        ps0 += __shfl_xor_sync(0xffffffffu, ps0, 1);
        ps0 += __shfl_xor_sync(0xffffffffu, ps0, 2);
        ps1 += __shfl_xor_sync(0xffffffffu, ps1, 1);
        ps1 += __shfl_xor_sync(0xffffffffu, ps1, 2);
        l0 = l0 * cr0 + ps0;
        l1 = l1 * cr1 + ps1;

#pragma unroll
        for (int nt = 0; nt < 16; nt++) {
            o[nt][0] *= cr0; o[nt][1] *= cr0;
            o[nt][2] *= cr1; o[nt][3] *= cr1;
        }

        asm volatile("cp.async.wait_group 1;");   // V(kb) resident
        __syncthreads();

#pragma unroll
        for (int ks2 = 0; ks2 < 8; ks2++) {
            uint32_t a[4];
            a[0] = __float_as_uint(sm[pbase + g * PSTR + ks2 * 8 + c]);
            a[1] = __float_as_uint(sm[pbase + (g + 8) * PSTR + ks2 * 8 + c]);
            a[2] = __float_as_uint(sm[pbase + g * PSTR + ks2 * 8 + c + 4]);
            a[3] = __float_as_uint(sm[pbase + (g + 8) * PSTR + ks2 * 8 + c + 4]);
#pragma unroll
            for (int nt = 0; nt < 16; nt++) {
                uint32_t bfr[2] = {
                    __float_as_uint(sm[SM_V + (ks2 * 8 + c) * VSTR + nt * 8 + g]),
                    __float_as_uint(sm[SM_V + (ks2 * 8 + c + 4) * VSTR + nt * 8 + g])};
                mma_tf32(o[nt], a, bfr);
            }
        }
        __syncthreads();   // also makes V+P region safe to reuse after the loop
    }

    // ---- fused epilogue: normalize + transpose to A-fragment layout ----
    // Per-warp 16x128 tile (stride 132) in the free V+P region.
    float il0 = 1.f / l0, il1 = 1.f / l1;
    float* tw = sm + SM_V + w * 2112;     // 16*132 floats per warp
#pragma unroll
    for (int nt = 0; nt < 16; nt++) {
        int col = nt * 8 + 2 * c;
        *reinterpret_cast<float2*>(&tw[g * 132 + col]) =
            make_float2(o[nt][0] * il0, o[nt][1] * il0);
        *reinterpret_cast<float2*>(&tw[(g + 8) * 132 + col]) =
            make_float2(o[nt][2] * il1, o[nt][3] * il1);
    }
    __syncwarp();

    // Emit fragment-major tf32: block (mbG, h*4+kc), frag f = w*4+ks,
    // float4 at lane*4: x=(g, k c), y=(g+8, k c), z=(g, k c+4), w=(g+8, k c+4)
    const int mbG = (b * SS_ + q0) >> 7;
#pragma unroll
    for (int kc = 0; kc < 4; kc++) {
#pragma unroll
        for (int ks = 0; ks < 4; ks++) {
            int kbase = kc * 32 + ks * 8 + c;
            uint4 ov;
            ov.x = f2tf(tw[g * 132 + kbase]);
            ov.y = f2tf(tw[(g + 8) * 132 + kbase]);
            ov.z = f2tf(tw[g * 132 + kbase + 4]);
            ov.w = f2tf(tw[(g + 8) * 132 + kbase + 4]);
            size_t dst = ((size_t)mbG * 64 + (h * 4 + kc)) * 4096
                       + (size_t)(w * 4 + ks) * 128 + lane * 4;
            *reinterpret_cast<uint4*>(attfm + dst) = ov;
        }
    }
}

// ===========================================================================
// Launch
// ===========================================================================
extern "C" void kernel_launch(void* const* d_in, const int* in_sizes, int n_in,
                              void* d_out, int out_size)
{
    const float* x      = (const float*)d_in[0];
    const float* W_qkv  = (const float*)d_in[1];
    const float* b_qkv  = (const float*)d_in[2];
    const float* W_out  = (const float*)d_in[3];
    const float* b_out  = (const float*)d_in[4];
    float* out          = (float*)d_out;

    float *qkv_p, *xfm_p, *attfm_p, *w1fm_p, *w2fm_p;
    cudaGetSymbolAddress((void**)&qkv_p,   g_qkv);
    cudaGetSymbolAddress((void**)&xfm_p,   g_xfm);
    cudaGetSymbolAddress((void**)&attfm_p, g_attfm);
    cudaGetSymbolAddress((void**)&w1fm_p,  g_w1fm);
    cudaGetSymbolAddress((void**)&w2fm_p,  g_w2fm);

    cudaFuncSetAttribute(gemm_fm_kernel,
                         cudaFuncAttributeMaxDynamicSharedMemorySize, GEMM_SMEM_BYTES);
    cudaFuncSetAttribute(flash_attn_tc_kernel,
                         cudaFuncAttributeMaxDynamicSharedMemorySize, AT_SMEM_BYTES);

    // One-time operand formatting (rounds to tf32 + fragment-major layout)
    prep_a_kernel<<<(M_TOT / 128) * (DD / 32), 256>>>(x, xfm_p, DD);
    prep_b_kernel<<<(N_QKV / 128) * (DD / 32), 256>>>(W_qkv, w1fm_p, N_QKV, DD);
    prep_b_kernel<<<(DD / 128) * (DD / 32), 256>>>(W_out, w2fm_p, DD, DD);

    // QKV projection (tf32-rounded output so attention skips cvt on K/V)
    gemm_fm_kernel<<<dim3(N_QKV / 128, M_TOT / 128), 256, GEMM_SMEM_BYTES>>>(
        xfm_p, w1fm_p, b_qkv, qkv_p, M_TOT, N_QKV, DD, 1);

    // Fused causal attention -> writes out-GEMM A-operand directly
    flash_attn_tc_kernel<<<dim3(SS_ / AT_BM, HH, BB), 256, AT_SMEM_BYTES>>>(qkv_p, attfm_p);

    // Output projection (raw fp32 output — final answer)
    gemm_fm_kernel<<<dim3(DD / 128, M_TOT / 128), 256, GEMM_SMEM_BYTES>>>(
        attfm_p, w2fm_p, b_out, out, M_TOT, DD, DD, 0);
}